// round 16
// baseline (speedup 1.0000x reference)
#include <cuda_runtime.h>
#include <cuda_fp16.h>
#include <math.h>
#include <stdint.h>

#define Bn 2
#define Sn 2048
#define En 1024
#define Hn 16
#define Dn 64
#define Mn (Bn*Sn)    // 4096
#define BHn (Bn*Hn)   // 32

// ---------------- scratch (device globals; no allocation allowed) ----------
__device__ __half g_q [(size_t)BHn*Sn*Dn];     // Q single
__device__ __half g_k [(size_t)BHn*Sn*Dn];     // K single
__device__ __half g_v [(size_t)BHn*Sn*Dn];     // V single
__device__ __half g_ctx[(size_t)Mn*En];        // ctx single
__device__ __half g_xq[(size_t)Mn*En], g_xk[(size_t)Mn*En], g_xv[(size_t)Mn*En];
__device__ __half g_Wq[(size_t)En*En], g_Wk[(size_t)En*En];
__device__ __half g_Wv[(size_t)En*En], g_Wo[(size_t)En*En];
__device__ float g_m[BHn*Sn];
__device__ float g_l[BHn*Sn];

// ---------------- PTX helpers (base-target only) ---------------------------
__device__ __forceinline__ uint32_t smem_u32(const void* p) {
    uint32_t a;
    asm("{ .reg .u64 t; cvta.to.shared.u64 t, %1; cvt.u32.u64 %0, t; }"
        : "=r"(a) : "l"(p));
    return a;
}
#define CP16(dst, src) \
    asm volatile("cp.async.cg.shared.global [%0], [%1], 16;\n" :: "r"(dst), "l"(src))
#define CP_COMMIT() asm volatile("cp.async.commit_group;\n" ::)
#define CP_WAIT0()  asm volatile("cp.async.wait_group 0;\n" ::)
#define CP_WAIT1()  asm volatile("cp.async.wait_group 1;\n" ::)
#define LDSM4(R0, R1, R2, R3, A) \
    asm volatile("ldmatrix.sync.aligned.m8n8.x4.shared.b16 {%0,%1,%2,%3}, [%4];" \
                 : "=r"(R0), "=r"(R1), "=r"(R2), "=r"(R3) : "r"(A))
#define LDSM4T(R0, R1, R2, R3, A) \
    asm volatile("ldmatrix.sync.aligned.m8n8.x4.trans.shared.b16 {%0,%1,%2,%3}, [%4];" \
                 : "=r"(R0), "=r"(R1), "=r"(R2), "=r"(R3) : "r"(A))

__device__ __forceinline__ void mma16816(float* c, const uint32_t* a, const uint32_t* b) {
    asm volatile(
        "mma.sync.aligned.m16n8k16.row.col.f32.f16.f16.f32 "
        "{%0,%1,%2,%3}, {%4,%5,%6,%7}, {%8,%9}, {%0,%1,%2,%3};"
        : "+f"(c[0]), "+f"(c[1]), "+f"(c[2]), "+f"(c[3])
        : "r"(a[0]), "r"(a[1]), "r"(a[2]), "r"(a[3]), "r"(b[0]), "r"(b[1]));
}

// ===========================================================================
// Batched splits: fp32 -> fp16
// ===========================================================================
__global__ void split_hi3(const float4* __restrict__ x0, const float4* __restrict__ x1,
                          const float4* __restrict__ x2,
                          __half2* __restrict__ h0, __half2* __restrict__ h1,
                          __half2* __restrict__ h2, int n4)
{
    int z = blockIdx.z;
    const float4* x = (z == 0) ? x0 : (z == 1) ? x1 : x2;
    __half2* hi = (z == 0) ? h0 : (z == 1) ? h1 : h2;
    int i = blockIdx.x * blockDim.x + threadIdx.x;
    if (i >= n4) return;
    float4 v = x[i];
    hi[i * 2 + 0] = __floats2half2_rn(v.x, v.y);
    hi[i * 2 + 1] = __floats2half2_rn(v.z, v.w);
}

__global__ void split_hiW4(const float4* __restrict__ x0, const float4* __restrict__ x1,
                           const float4* __restrict__ x2, const float4* __restrict__ x3,
                           __half2* __restrict__ h0, __half2* __restrict__ h1,
                           __half2* __restrict__ h2, __half2* __restrict__ h3, int n4)
{
    int z = blockIdx.z;
    const float4* x = (z == 0) ? x0 : (z == 1) ? x1 : (z == 2) ? x2 : x3;
    __half2* hi = (z == 0) ? h0 : (z == 1) ? h1 : (z == 2) ? h2 : h3;
    int i = blockIdx.x * blockDim.x + threadIdx.x;
    if (i >= n4) return;
    float4 v = x[i];
    hi[i * 2 + 0] = __floats2half2_rn(v.x, v.y);
    hi[i * 2 + 1] = __floats2half2_rn(v.z, v.w);
}

// ===========================================================================
// 1-term fp16 GEMM core: 128x128 tile, 8 warps, KC=64, 3-buffer / 2-in-flight
// cp.async pipeline.  Steady-state wait = WAIT1 (fill(s) landed, fill(s+1)
// still in flight ~1 stage ahead of use); WAIT0 only at the final stage.
// ===========================================================================
#define KC     64
#define TROW   144               // 64 halves = 128 B, padded to 144
#define TTEN   (128 * TROW)      // 18432
#define G1STG  (2 * TTEN)        // A | W        = 36864
#define NPIPE  3
#define G1SMEM (NPIPE * G1STG)   // 110592

__device__ __forceinline__
void gemm_core(const __half* __restrict__ Ah, const __half* __restrict__ Wh,
               const float* __restrict__ bias,
               float* __restrict__ out, __half* __restrict__ oH, int mode,
               char* sm)
{
    uint32_t sbase = smem_u32(sm);
    const int tid = threadIdx.x, wid = tid >> 5, lid = tid & 31;
    const int n0 = blockIdx.x * 128, m0 = blockIdx.y * 128;
    const int wm = wid & 3, wn = wid >> 2;

    const char* src[2] = { (const char*)(Ah + (size_t)m0 * En),
                           (const char*)(Wh + (size_t)n0 * En) };

    auto fill = [&](int buf, int ks) {
        uint32_t st = sbase + buf * G1STG;
        size_t koff = (size_t)ks * (KC * 2);   // 128 B per stage step
#pragma unroll
        for (int it = 0; it < 8; it++) {
            int idx = tid + it * 256;          // 0..2047 chunks of 16B
            int t = idx >> 10, rc = idx & 1023;
            int r = rc >> 3, c = rc & 7;
            CP16(st + t * TTEN + r * TROW + c * 16,
                 src[t] + koff + (size_t)r * 2048 + c * 16);
        }
        CP_COMMIT();
    };

    float acc[2][8][4];
#pragma unroll
    for (int mi = 0; mi < 2; mi++)
#pragma unroll
        for (int nj = 0; nj < 8; nj++)
#pragma unroll
            for (int q = 0; q < 4; q++) acc[mi][nj][q] = 0.f;

    fill(0, 0); fill(1, 1);                 // 2-deep prologue
    const int NST = En / KC;                // 16 stages
    for (int s = 0; s < NST; s++) {
        int buf = s % 3;
        if (s + 1 < NST) CP_WAIT1();        // fill(s) landed; fill(s+1) in flight
        else             CP_WAIT0();        // last stage: drain everything
        __syncthreads();                    // also guards buf (s-1)%3 reuse below
        if (s + 2 < NST) fill((s + 2) % 3, s + 2);
        uint32_t Ab = sbase + buf * G1STG;
        uint32_t Wb = Ab + TTEN;
#pragma unroll
        for (int kb = 0; kb < KC; kb += 16) {
            uint32_t ah[2][4];
            int arow = wm * 32 + (lid & 7) + ((lid >> 3) & 1) * 8;
            int acol = kb + (lid >> 4) * 8;
            uint32_t aoff = arow * TROW + acol * 2;
#pragma unroll
            for (int mi = 0; mi < 2; mi++)
                LDSM4(ah[mi][0], ah[mi][1], ah[mi][2], ah[mi][3],
                      Ab + mi * (16 * TROW) + aoff);
            uint32_t bh[8][2];
            int brow = wn * 64 + (lid & 7) + (lid >> 4) * 8;
            int bcol = kb + ((lid >> 3) & 1) * 8;
            uint32_t boff = brow * TROW + bcol * 2;
#pragma unroll
            for (int p = 0; p < 4; p++) {
                uint32_t r0, r1, r2, r3;
                LDSM4(r0, r1, r2, r3, Wb + p * (16 * TROW) + boff);
                bh[p * 2][0] = r0; bh[p * 2][1] = r1;
                bh[p * 2 + 1][0] = r2; bh[p * 2 + 1][1] = r3;
            }
#pragma unroll
            for (int mi = 0; mi < 2; mi++)
#pragma unroll
                for (int nj = 0; nj < 8; nj++)
                    mma16816(acc[mi][nj], ah[mi], bh[nj]);
        }
    }

    int m_base = m0 + wm * 32, n_base = n0 + wn * 64;
    int rsub = lid >> 2, csub = (lid & 3) * 2;
#pragma unroll
    for (int mi = 0; mi < 2; mi++)
#pragma unroll
        for (int nj = 0; nj < 8; nj++) {
            int cc = n_base + nj * 8 + csub;
            float bx = bias[cc], by = bias[cc + 1];
#pragma unroll
            for (int half = 0; half < 2; half++) {
                int m = m_base + mi * 16 + rsub + half * 8;
                float vx = acc[mi][nj][half * 2 + 0] + bx;
                float vy = acc[mi][nj][half * 2 + 1] + by;
                if (mode == 0) {
                    float2 v; v.x = vx; v.y = vy;
                    *(float2*)&out[(size_t)m * En + cc] = v;
                } else {
                    int h = cc >> 6, d = cc & 63;
                    int b = m >> 11, ss = m & 2047;
                    size_t idx = (((size_t)b * Hn + h) * Sn + ss) * Dn + d;
                    __half2 hv = __floats2half2_rn(vx, vy);
                    *(uint32_t*)&oH[idx] = *(uint32_t*)&hv;
                }
            }
        }
}

// Batched QKV projection: gridDim.z selects (A, W, bias, out).
__global__ __launch_bounds__(256, 2)
void gemm_qkv(const __half* __restrict__ A0, const __half* __restrict__ A1,
              const __half* __restrict__ A2,
              const __half* __restrict__ W0, const __half* __restrict__ W1,
              const __half* __restrict__ W2,
              const float* __restrict__ b0, const float* __restrict__ b1,
              const float* __restrict__ b2,
              __half* __restrict__ o0, __half* __restrict__ o1,
              __half* __restrict__ o2)
{
    extern __shared__ __align__(128) char sm[];
    int z = blockIdx.z;
    const __half* A = (z == 0) ? A0 : (z == 1) ? A1 : A2;
    const __half* W = (z == 0) ? W0 : (z == 1) ? W1 : W2;
    const float* b  = (z == 0) ? b0 : (z == 1) ? b1 : b2;
    __half* o       = (z == 0) ? o0 : (z == 1) ? o1 : o2;
    gemm_core(A, W, b, nullptr, o, 1, sm);
}

// Single GEMM (used for the O projection, fp32 out).
__global__ __launch_bounds__(256, 2)
void gemm_t1(const __half* __restrict__ Ah, const __half* __restrict__ Wh,
             const float* __restrict__ bias,
             float* __restrict__ out, __half* __restrict__ oH, int mode)
{
    extern __shared__ __align__(128) char sm[];
    gemm_core(Ah, Wh, bias, out, oH, mode, sm);
}

// ===========================================================================
// Flash pass 1: QK 1-term, PV 1-term (all single fp16). 128 q-rows/CTA,
// 8 warps, 64-key tiles, 3-stage cp.async KV pipeline. ctx single fp16.
// (Tail wait fixed: WAIT0 on the final tile.)
// ===========================================================================
#define KR 144
#define QSM (128*KR)                // 18432
#define KVT (64*KR)                 // 9216
#define KVSTG (2*KVT)               // 18432 : k | v
#define P1SMEM (QSM + 3*KVSTG)      // 73728

__global__ __launch_bounds__(256, 2)
void attn_pass1(const __half* __restrict__ qh, const __half* __restrict__ kh,
                const __half* __restrict__ vh,
                __half* __restrict__ ctx,
                float* __restrict__ gm, float* __restrict__ gl)
{
    extern __shared__ __align__(128) char sm[];
    uint32_t sb = smem_u32(sm);
    const int tid = threadIdx.x, wid = tid >> 5, lid = tid & 31;
    const int qt = (gridDim.x - 1) - blockIdx.x;
    const int bh = blockIdx.y;
    const int q0 = qt * 128;
    const size_t hbase = (size_t)bh * Sn * Dn;

    const char* gq = (const char*)(qh + hbase + (size_t)q0 * Dn);
    const char* gkv[2] = { (const char*)(kh + hbase), (const char*)(vh + hbase) };

    uint32_t Qb = sb, KVb = sb + QSM;

#pragma unroll
    for (int i = 0; i < 4; i++) {
        int idx = tid + i * 256;
        int r = idx >> 3, c = idx & 7;
        CP16(Qb + r * KR + c * 16, gq + (size_t)r * 128 + c * 16);
    }
    auto fillKV = [&](int buf, int kt) {
        uint32_t st = KVb + buf * KVSTG;
        size_t gof = (size_t)kt * 64 * 128;
#pragma unroll
        for (int i = 0; i < 4; i++) {
            int idx = tid + i * 256;      // 0..1023
            int t = idx >> 9, rc = idx & 511, r = rc >> 3, c = rc & 7;
            CP16(st + t * KVT + r * KR + c * 16, gkv[t] + gof + (size_t)r * 128 + c * 16);
        }
        CP_COMMIT();
    };
    const int ktmax = 2 * qt + 1;
    fillKV(0, 0);
    fillKV(1, 1);

    uint32_t qf[4][4];
    float o[8][4];
#pragma unroll
    for (int nj = 0; nj < 8; nj++)
#pragma unroll
        for (int e = 0; e < 4; e++) o[nj][e] = 0.f;
    float mrow[2] = {-1e30f, -1e30f}, lrow[2] = {0.f, 0.f};

    for (int kt = 0; kt <= ktmax; kt++) {
        int buf = kt % 3;
        if (kt < ktmax) CP_WAIT1();
        else            CP_WAIT0();
        __syncthreads();
        if (kt + 2 <= ktmax) fillKV((kt + 2) % 3, kt + 2);
        if (kt == 0) {
            int ar = wid * 16 + (lid & 7) + ((lid >> 3) & 1) * 8;
#pragma unroll
            for (int t = 0; t < 4; t++)
                LDSM4(qf[t][0], qf[t][1], qf[t][2], qf[t][3],
                      Qb + ar * KR + t * 32 + (lid >> 4) * 16);
        }
        uint32_t Kb_ = KVb + buf * KVSTG;
        uint32_t Vb_ = Kb_ + KVT;

        // ---- S = Q K^T (1-term) ----
        float sf[8][4];
#pragma unroll
        for (int nj = 0; nj < 8; nj++)
#pragma unroll
            for (int e = 0; e < 4; e++) sf[nj][e] = 0.f;

        int br = (lid & 7) + (lid >> 4) * 8;
#pragma unroll
        for (int t = 0; t < 4; t++) {
            int bc = t * 32 + ((lid >> 3) & 1) * 16;
#pragma unroll
            for (int p = 0; p < 4; p++) {
                uint32_t b0, b1, b2, b3;
                LDSM4(b0, b1, b2, b3, Kb_ + (p * 16 + br) * KR + bc);
                uint32_t B0[2] = {b0, b1}, B1[2] = {b2, b3};
                mma16816(sf[2*p],   qf[t], B0);
                mma16816(sf[2*p+1], qf[t], B1);
            }
        }

        // ---- online softmax ----
        const float scale = 0.125f;
        bool domask = (kt * 64 + 63) > (q0 + wid * 16);
        float tmax[2] = {-1e30f, -1e30f};
#pragma unroll
        for (int nj = 0; nj < 8; nj++)
#pragma unroll
            for (int e = 0; e < 4; e++) {
                float s = sf[nj][e] * scale;
                if (domask) {
                    int kc = kt * 64 + nj * 8 + 2 * (lid & 3) + (e & 1);
                    int qr = q0 + wid * 16 + (lid >> 2) + 8 * (e >> 1);
                    if (kc > qr) s = -1e9f;
                }
                sf[nj][e] = s;
                tmax[e >> 1] = fmaxf(tmax[e >> 1], s);
            }
#pragma unroll
        for (int h = 0; h < 2; h++) {
            tmax[h] = fmaxf(tmax[h], __shfl_xor_sync(0xffffffffu, tmax[h], 1));
            tmax[h] = fmaxf(tmax[h], __shfl_xor_sync(0xffffffffu, tmax[h], 2));
        }
        float fac[2], rsum[2] = {0.f, 0.f};
#pragma unroll
        for (int h = 0; h < 2; h++) {
            float mn = fmaxf(mrow[h], tmax[h]);
            fac[h] = __expf(mrow[h] - mn);
            mrow[h] = mn;
        }
#pragma unroll
        for (int nj = 0; nj < 8; nj++)
#pragma unroll
            for (int e = 0; e < 4; e++) {
                float p = __expf(sf[nj][e] - mrow[e >> 1]);
                sf[nj][e] = p;
                rsum[e >> 1] += p;
            }
#pragma unroll
        for (int h = 0; h < 2; h++) {
            rsum[h] += __shfl_xor_sync(0xffffffffu, rsum[h], 1);
            rsum[h] += __shfl_xor_sync(0xffffffffu, rsum[h], 2);
            lrow[h] = lrow[h] * fac[h] + rsum[h];
        }
#pragma unroll
        for (int nj = 0; nj < 8; nj++)
#pragma unroll
            for (int e = 0; e < 4; e++) o[nj][e] *= fac[e >> 1];

        // ---- O += P V (1-term, P single fp16) ----
        int vr = (lid & 7) + ((lid >> 3) & 1) * 8;
        int vc = (lid >> 4) * 16;
#pragma unroll
        for (int t = 0; t < 4; t++) {
            uint32_t pha[4];
#pragma unroll
            for (int u = 0; u < 2; u++) {
                __half2 h01 = __floats2half2_rn(sf[2*t+u][0], sf[2*t+u][1]);
                __half2 h23 = __floats2half2_rn(sf[2*t+u][2], sf[2*t+u][3]);
                pha[2*u+0] = *(uint32_t*)&h01;
                pha[2*u+1] = *(uint32_t*)&h23;
            }
#pragma unroll
            for (int p = 0; p < 4; p++) {
                uint32_t b0, b1, b2, b3;
                LDSM4T(b0, b1, b2, b3, Vb_ + (t * 16 + vr) * KR + p * 32 + vc);
                uint32_t B0[2] = {b0, b1}, B1[2] = {b2, b3};
                mma16816(o[2*p],   pha, B0);
                mma16816(o[2*p+1], pha, B1);
            }
        }
    }

    float invl[2] = {1.f / lrow[0], 1.f / lrow[1]};
    int b = bh >> 4, hh = bh & 15;
#pragma unroll
    for (int h = 0; h < 2; h++) {
        int r = q0 + wid * 16 + (lid >> 2) + 8 * h;
        size_t rowb = ((size_t)b * Sn + r) * En + hh * 64;
#pragma unroll
        for (int nj = 0; nj < 8; nj++) {
            int cc = nj * 8 + 2 * (lid & 3);
            __half2 hv = __floats2half2_rn(o[nj][2*h]   * invl[h],
                                           o[nj][2*h+1] * invl[h]);
            *(uint32_t*)&ctx[rowb + cc] = *(uint32_t*)&hv;
        }
        if ((lid & 3) == 0) {
            gm[bh * Sn + r] = mrow[h];
            gl[bh * Sn + r] = lrow[h];
        }
    }
}

// ===========================================================================
// Zero-fill strictly-upper 128x128 tiles of attn (overlaps pass1).
// ===========================================================================
__global__ __launch_bounds__(256)
void attn_zerofill(float* __restrict__ attn)
{
    const int kt = blockIdx.x, qt = blockIdx.y, bh = blockIdx.z;
    if (kt <= qt) return;
    float* arow = attn + (size_t)bh * Sn * Sn;
    const int q0 = qt * 128, k0 = kt * 128;
    float4 z = make_float4(0.f, 0.f, 0.f, 0.f);
#pragma unroll
    for (int i = 0; i < 16; i++) {
        int idx = threadIdx.x + i * 256;
        int r = idx >> 5, c4 = (idx & 31) << 2;
        *(float4*)&arow[(size_t)(q0 + r) * Sn + k0 + c4] = z;
    }
}

// ===========================================================================
// Pass 2: recompute P (1-term QK), write lower-triangle attn tiles only.
// ===========================================================================
#define AWT   (128*KR)       // 18432
#define AWSMEM (2*AWT)       // 36864 : Q | K

__global__ __launch_bounds__(256, 2)
void attn_write(const __half* __restrict__ qh, const __half* __restrict__ kh,
                const float* __restrict__ gm, const float* __restrict__ gl,
                float* __restrict__ attn)
{
    const int kt = blockIdx.x, qt = blockIdx.y, bh = blockIdx.z;
    if (kt > qt) return;     // upper triangle handled by attn_zerofill
    const int tid = threadIdx.x, wid = tid >> 5, lid = tid & 31;
    const int q0 = qt * 128, k0 = kt * 128;
    float* arow = attn + (size_t)bh * Sn * Sn;

    extern __shared__ __align__(128) char sm[];
    uint32_t sb = smem_u32(sm);
    const size_t hbase = (size_t)bh * Sn * Dn;
    const char* gsrc[2] = { (const char*)(qh + hbase + (size_t)q0 * Dn),
                            (const char*)(kh + hbase + (size_t)k0 * Dn) };
#pragma unroll
    for (int i = 0; i < 8; i++) {
        int idx = tid + i * 256;
        int t = idx >> 10, rc = idx & 1023, r = rc >> 3, c = rc & 7;
        CP16(sb + t * AWT + r * KR + c * 16, gsrc[t] + (size_t)r * 128 + c * 16);
    }
    CP_COMMIT(); CP_WAIT0();
    __syncthreads();

    uint32_t Qh_ = sb, Kh_ = sb + AWT;

    uint32_t qf[4][4];
    int ar = wid * 16 + (lid & 7) + ((lid >> 3) & 1) * 8;
#pragma unroll
    for (int t = 0; t < 4; t++)
        LDSM4(qf[t][0], qf[t][1], qf[t][2], qf[t][3],
              Qh_ + ar * KR + t * 32 + (lid >> 4) * 16);

    float sf[16][4];
#pragma unroll
    for (int nj = 0; nj < 16; nj++)
#pragma unroll
        for (int e = 0; e < 4; e++) sf[nj][e] = 0.f;

    int br = (lid & 7) + (lid >> 4) * 8;
#pragma unroll
    for (int t = 0; t < 4; t++) {
        int bc = t * 32 + ((lid >> 3) & 1) * 16;
#pragma unroll
        for (int p = 0; p < 8; p++) {
            uint32_t b0, b1, b2, b3;
            LDSM4(b0, b1, b2, b3, Kh_ + (p * 16 + br) * KR + bc);
            uint32_t B0[2] = {b0, b1}, B1[2] = {b2, b3};
            mma16816(sf[2*p],   qf[t], B0);
            mma16816(sf[2*p+1], qf[t], B1);
        }
    }

    float mr2[2], inv2[2];
#pragma unroll
    for (int h = 0; h < 2; h++) {
        int r = q0 + wid * 16 + (lid >> 2) + 8 * h;
        mr2[h]  = gm[bh * Sn + r];
        inv2[h] = 1.f / gl[bh * Sn + r];
    }
    const float scale = 0.125f;
    bool diag = (kt == qt);
#pragma unroll
    for (int nj = 0; nj < 16; nj++) {
#pragma unroll
        for (int h = 0; h < 2; h++) {
            int r  = q0 + wid * 16 + (lid >> 2) + 8 * h;
            int cc = k0 + nj * 8 + 2 * (lid & 3);
            float p0 = __expf(sf[nj][2*h]   * scale - mr2[h]) * inv2[h];
            float p1 = __expf(sf[nj][2*h+1] * scale - mr2[h]) * inv2[h];
            if (diag) {
                if (cc > r)     p0 = 0.f;
                if (cc + 1 > r) p1 = 0.f;
            }
            float2 v; v.x = p0; v.y = p1;
            *(float2*)&arow[(size_t)r * Sn + cc] = v;
        }
    }
}

// ---------------------------------------------------------------------------
extern "C" void kernel_launch(void* const* d_in, const int* in_sizes, int n_in,
                              void* d_out, int out_size)
{
    const float* query = (const float*)d_in[0];
    const float* key   = (const float*)d_in[1];
    const float* value = (const float*)d_in[2];
    // d_in[3] = causal mask, applied analytically
    const float* Wq = (const float*)d_in[4];
    const float* bq = (const float*)d_in[5];
    const float* Wk = (const float*)d_in[6];
    const float* bk = (const float*)d_in[7];
    const float* Wv = (const float*)d_in[8];
    const float* bv = (const float*)d_in[9];
    const float* Wo = (const float*)d_in[10];
    const float* bo = (const float*)d_in[11];

    __half *pq,*pk,*pv,*pctx;
    __half *pxq,*pxk,*pxv,*pWq,*pWk,*pWv,*pWo;
    float *pm, *pl;
    cudaGetSymbolAddress((void**)&pq,  g_q);   cudaGetSymbolAddress((void**)&pk,  g_k);
    cudaGetSymbolAddress((void**)&pv,  g_v);   cudaGetSymbolAddress((void**)&pctx, g_ctx);
    cudaGetSymbolAddress((void**)&pxq, g_xq);  cudaGetSymbolAddress((void**)&pxk, g_xk);
    cudaGetSymbolAddress((void**)&pxv, g_xv);
    cudaGetSymbolAddress((void**)&pWq, g_Wq);  cudaGetSymbolAddress((void**)&pWk, g_Wk);
    cudaGetSymbolAddress((void**)&pWv, g_Wv);  cudaGetSymbolAddress((void**)&pWo, g_Wo);
    cudaGetSymbolAddress((void**)&pm, g_m);    cudaGetSymbolAddress((void**)&pl, g_l);

    static bool init_done = false;
    static cudaStream_t s1;
    static cudaEvent_t e0, e1, e3, e4;
    if (!init_done) {
        cudaFuncSetAttribute(gemm_qkv,
                             cudaFuncAttributeMaxDynamicSharedMemorySize, G1SMEM);
        cudaFuncSetAttribute(gemm_t1,
                             cudaFuncAttributeMaxDynamicSharedMemorySize, G1SMEM);
        cudaFuncSetAttribute(attn_pass1,
                             cudaFuncAttributeMaxDynamicSharedMemorySize, P1SMEM);
        cudaFuncSetAttribute(attn_write,
                             cudaFuncAttributeMaxDynamicSharedMemorySize, AWSMEM);
        cudaStreamCreateWithFlags(&s1, cudaStreamNonBlocking);
        cudaEventCreateWithFlags(&e0, cudaEventDisableTiming);
        cudaEventCreateWithFlags(&e1, cudaEventDisableTiming);
        cudaEventCreateWithFlags(&e3, cudaEventDisableTiming);
        cudaEventCreateWithFlags(&e4, cudaEventDisableTiming);
        init_done = true;
    }

    const int NA4 = (Mn * En) / 4;
    const int NW4 = (En * En) / 4;
    dim3 gg3(En / 128, Mn / 128, 3);   // (8, 32, 3) = 768 CTAs
    dim3 gg (En / 128, Mn / 128);      // (8, 32)

    const size_t OUT_ELEMS  = (size_t)Bn * Sn * En;
    const size_t ATTN_ELEMS = (size_t)BHn * Sn * Sn;
    float* outp  = (float*)d_out;
    float* attnp = nullptr;
    if ((size_t)out_size >= OUT_ELEMS + ATTN_ELEMS) {
        attnp = outp + OUT_ELEMS;
    } else if ((size_t)out_size == ATTN_ELEMS) {
        attnp = outp; outp = nullptr;
    }

    // ---- phase 1: batched splits (W-splits on s1 concurrent with A-splits) ----
    cudaEventRecord(e0, 0);
    cudaStreamWaitEvent(s1, e0, 0);

    split_hiW4<<<dim3((NW4 + 255) / 256, 1, 4), 256, 0, s1>>>(
        (const float4*)Wq, (const float4*)Wk, (const float4*)Wv, (const float4*)Wo,
        (__half2*)pWq, (__half2*)pWk, (__half2*)pWv, (__half2*)pWo, NW4);
    cudaEventRecord(e1, s1);

    split_hi3<<<dim3((NA4 + 255) / 256, 1, 3), 256>>>(
        (const float4*)query, (const float4*)key, (const float4*)value,
        (__half2*)pxq, (__half2*)pxk, (__half2*)pxv, NA4);

    // zero-fill upper triangle on s1 (overlaps QKV gemm + pass1)
    if (attnp)
        attn_zerofill<<<dim3(16, 16, BHn), 256, 0, s1>>>(attnp);

    // ---- batched QKV projection (one launch, 768 CTAs) ----
    cudaStreamWaitEvent(0, e1, 0);
    gemm_qkv<<<gg3, 256, G1SMEM>>>(pxq, pxk, pxv, pWq, pWk, pWv,
                                   bq, bk, bv, pq, pk, pv);

    // ---- pass 1 ----
    attn_pass1<<<dim3(Sn / 128, BHn), 256, P1SMEM>>>(pq, pk, pv, pctx, pm, pl);
    cudaEventRecord(e3, 0);

    // ---- attn_write (lower triangle) on s1 overlaps O-proj (tensor) ----
    if (attnp) {
        cudaStreamWaitEvent(s1, e3, 0);
        attn_write<<<dim3(Sn / 128, Sn / 128, BHn), 256, AWSMEM, s1>>>(
            pq, pk, pm, pl, attnp);
        cudaEventRecord(e4, s1);
    }
    if (outp)
        gemm_t1<<<gg, 256, G1SMEM>>>(pctx, pWo, bo, outp, nullptr, 0);
    if (attnp)
        cudaStreamWaitEvent(0, e4, 0);
}